// round 8
// baseline (speedup 1.0000x reference)
#include <cuda_runtime.h>
#include <math.h>
#include <stdint.h>

#define NROWS 8192
#define DDIM  128
#define NT    64          // 8192/128 tiles per side
#define NPAIR 2080        // 64*65/2

// Scratch (__device__ globals: allocation-free rule)
__device__ uint8_t g_h1q[NROWS * DDIM];   // int8 of round(127*normalized h1)
__device__ uint8_t g_h2q[NROWS * DDIM];
__device__ float g_R[4 * NROWS];          // [R11 | R12row | R12col | R22]
__device__ float g_diag[NROWS];

// ---------------------------------------------------------------------------
__device__ __forceinline__ uint32_t smem_u32(const void* p) {
    uint32_t a;
    asm("{ .reg .u64 t; cvta.to.shared.u64 t, %1; cvt.u32.u64 %0, t; }"
        : "=r"(a) : "l"(p));
    return a;
}

__device__ __forceinline__ void ldsm_x4(uint32_t& r0, uint32_t& r1,
                                        uint32_t& r2, uint32_t& r3, uint32_t addr) {
    asm volatile("ldmatrix.sync.aligned.m8n8.x4.shared.b16 {%0,%1,%2,%3}, [%4];"
                 : "=r"(r0), "=r"(r1), "=r"(r2), "=r"(r3) : "r"(addr));
}

// int8 IMMA: m16n8k32, s32 accumulate
__device__ __forceinline__ void mma_s8(int* d, const uint32_t* a, const uint32_t* b) {
    asm volatile(
        "mma.sync.aligned.m16n8k32.row.col.s32.s8.s8.s32 "
        "{%0,%1,%2,%3}, {%4,%5,%6,%7}, {%8,%9}, {%0,%1,%2,%3};"
        : "+r"(d[0]), "+r"(d[1]), "+r"(d[2]), "+r"(d[3])
        : "r"(a[0]), "r"(a[1]), "r"(a[2]), "r"(a[3]), "r"(b[0]), "r"(b[1]));
}

// ---------------------------------------------------------------------------
// Row-normalize -> int8 (round(127*x_n)); exact fp32 diag; zero g_R and out.
// ---------------------------------------------------------------------------
__global__ void norm_kernel(const float* __restrict__ h1,
                            const float* __restrict__ h2,
                            float* __restrict__ out) {
    int gt   = blockIdx.x * blockDim.x + threadIdx.x;
    int w    = gt >> 5;
    int lane = gt & 31;

    if (gt < 4 * NROWS) g_R[gt] = 0.0f;
    if (gt == 0) out[0] = 0.0f;
    if (w >= NROWS) return;

    float4 v1 = ((const float4*)(h1 + (size_t)w * DDIM))[lane];
    float4 v2 = ((const float4*)(h2 + (size_t)w * DDIM))[lane];

    float ss1 = v1.x*v1.x + v1.y*v1.y + v1.z*v1.z + v1.w*v1.w;
    float ss2 = v2.x*v2.x + v2.y*v2.y + v2.z*v2.z + v2.w*v2.w;
    float dt  = v1.x*v2.x + v1.y*v2.y + v1.z*v2.z + v1.w*v2.w;

    #pragma unroll
    for (int m = 16; m > 0; m >>= 1) {
        ss1 += __shfl_xor_sync(0xffffffffu, ss1, m);
        ss2 += __shfl_xor_sync(0xffffffffu, ss2, m);
        dt  += __shfl_xor_sync(0xffffffffu, dt,  m);
    }

    float in1 = 1.0f / fmaxf(sqrtf(ss1), 1e-12f);
    float in2 = 1.0f / fmaxf(sqrtf(ss2), 1e-12f);
    float s1 = 127.0f * in1, s2 = 127.0f * in2;

    int q0 = __float2int_rn(v1.x * s1), q1 = __float2int_rn(v1.y * s1);
    int q2 = __float2int_rn(v1.z * s1), q3 = __float2int_rn(v1.w * s1);
    ((uint32_t*)(g_h1q + (size_t)w * DDIM))[lane] =
        (q0 & 255) | ((q1 & 255) << 8) | ((q2 & 255) << 16) | ((uint32_t)(q3 & 255) << 24);

    q0 = __float2int_rn(v2.x * s2); q1 = __float2int_rn(v2.y * s2);
    q2 = __float2int_rn(v2.z * s2); q3 = __float2int_rn(v2.w * s2);
    ((uint32_t*)(g_h2q + (size_t)w * DDIM))[lane] =
        (q0 & 255) | ((q1 & 255) << 8) | ((q2 & 255) << 16) | ((uint32_t)(q3 & 255) << 24);

    if (lane == 0) g_diag[w] = dt * in1 * in2;
}

// ---------------------------------------------------------------------------
// Pair-CTA kernel, int8 IMMA. One CTA per tile pair (I<=J).
// Two passes sharing A-fragments:
//   pass0 (A=h1[I]): q0: B=h1[J] (S11)  q1: B=h2[J] (S12)
//   pass1 (A=h2[I]): q0: B=h2[J] (S22)  q1: B=h1[J] (S21, offd only)
// Row sums -> I-side, col sums -> J-side.
// exp(5*s) = 2^(acc * 5*log2(e)/127^2), acc = s32 dot of quantized rows.
// ---------------------------------------------------------------------------
#define SM_TILE 16384
#define SM_TOTAL (4 * SM_TILE)

__global__ void __launch_bounds__(256, 3) mma_exp_kernel() {
    extern __shared__ char smem[];
    const uint32_t sb = smem_u32(smem);

    int tid  = threadIdx.x;
    int wid  = tid >> 5;
    int lane = tid & 31;

    // Decode triangular pair index -> (I, J), I<=J
    int p = blockIdx.x, I = 0;
    while (p >= NT - I) { p -= NT - I; I++; }
    int J = I + p;
    bool offd = (J > I);

    // ---- Load 4 tiles (h1[I], h2[I], h1[J], h2[J]) into swizzled SMEM
    {
        const uint4* base[4] = {
            (const uint4*)(g_h1q + (size_t)I * 128 * DDIM),
            (const uint4*)(g_h2q + (size_t)I * 128 * DDIM),
            (const uint4*)(g_h1q + (size_t)J * 128 * DDIM),
            (const uint4*)(g_h2q + (size_t)J * 128 * DDIM)
        };
        #pragma unroll
        for (int it = 0; it < 16; it++) {
            int tile = it >> 2;
            int lidx = tid + (it & 3) * 256;
            int r = lidx >> 3, c = lidx & 7;
            uint32_t off = (uint32_t)tile * SM_TILE + (uint32_t)r * 128u
                         + (uint32_t)((c ^ (r & 7)) << 4);
            *(uint4*)(smem + off) = base[tile][lidx];
        }
    }
    __syncthreads();

    int wm = wid >> 2;          // 0..1  (M)
    int wn = wid & 3;           // 0..3  (N)
    int a_r  = wm * 64 + (lane & 15);
    int a_cp = lane >> 4;
    int b_r  = wn * 32 + ((lane >> 4) << 3) + (lane & 7);
    int b_cp = (lane >> 3) & 1;

    const float SCL = 4.4723637e-4f;   // 5*log2(e)/(127*127)

    #pragma unroll 1
    for (int pass = 0; pass < 2; pass++) {
        uint32_t As  = (uint32_t)pass * SM_TILE;
        uint32_t Bs0 = (pass == 0) ? 2u * SM_TILE : 3u * SM_TILE;
        uint32_t Bs1 = (pass == 0) ? 3u * SM_TILE : 2u * SM_TILE;

        float *rowp0, *colp0, *rowp1, *colp1;
        if (pass == 0) {
            rowp0 = g_R + I*128;             colp0 = g_R + J*128;             // S11
            rowp1 = g_R + NROWS + I*128;     colp1 = g_R + 2*NROWS + J*128;   // S12
        } else {
            rowp0 = g_R + 3*NROWS + I*128;   colp0 = g_R + 3*NROWS + J*128;   // S22
            rowp1 = g_R + 2*NROWS + I*128;   colp1 = g_R + NROWS + J*128;     // S21
        }
        int nq = (pass == 1 && !offd) ? 1 : 2;

        float cp[2][4][2];
        #pragma unroll
        for (int q = 0; q < 2; q++)
            #pragma unroll
            for (int nt = 0; nt < 4; nt++) { cp[q][nt][0] = 0.f; cp[q][nt][1] = 0.f; }

        #pragma unroll
        for (int mt = 0; mt < 4; mt++) {
            // A fragments for this strip (shared by both q GEMMs)
            uint32_t a[4][4];
            int r = a_r + mt * 16;
            #pragma unroll
            for (int ks = 0; ks < 4; ks++) {
                uint32_t addr = sb + As + (uint32_t)r * 128u
                              + (uint32_t)(((ks * 2 + a_cp) ^ (r & 7)) << 4);
                ldsm_x4(a[ks][0], a[ks][1], a[ks][2], a[ks][3], addr);
            }

            #pragma unroll
            for (int q = 0; q < 2; q++) {
                if (q >= nq) break;
                uint32_t Bs = q ? Bs1 : Bs0;

                int acc[4][4];
                #pragma unroll
                for (int nt = 0; nt < 4; nt++)
                    #pragma unroll
                    for (int v = 0; v < 4; v++) acc[nt][v] = 0;

                #pragma unroll
                for (int ks = 0; ks < 4; ks++) {
                    uint32_t b[4][2];
                    #pragma unroll
                    for (int np = 0; np < 2; np++) {
                        int br = b_r + np * 16;
                        uint32_t addr = sb + Bs + (uint32_t)br * 128u
                                      + (uint32_t)(((ks * 2 + b_cp) ^ (br & 7)) << 4);
                        ldsm_x4(b[np*2][0], b[np*2][1], b[np*2+1][0], b[np*2+1][1], addr);
                    }
                    #pragma unroll
                    for (int nt = 0; nt < 4; nt++)
                        mma_s8(acc[nt], a[ks], b[nt]);
                }

                // ---- Epilogue: e = 2^(acc*SCL); row + col partial sums
                float rp0 = 0.f, rp1 = 0.f;
                #pragma unroll
                for (int nt = 0; nt < 4; nt++) {
                    float e0, e1, e2, e3;
                    asm("ex2.approx.f32 %0, %1;" : "=f"(e0) : "f"((float)acc[nt][0] * SCL));
                    asm("ex2.approx.f32 %0, %1;" : "=f"(e1) : "f"((float)acc[nt][1] * SCL));
                    asm("ex2.approx.f32 %0, %1;" : "=f"(e2) : "f"((float)acc[nt][2] * SCL));
                    asm("ex2.approx.f32 %0, %1;" : "=f"(e3) : "f"((float)acc[nt][3] * SCL));
                    rp0 += e0 + e1;
                    rp1 += e2 + e3;
                    cp[q][nt][0] += e0 + e2;
                    cp[q][nt][1] += e1 + e3;
                }
                rp0 += __shfl_xor_sync(0xffffffffu, rp0, 1);
                rp0 += __shfl_xor_sync(0xffffffffu, rp0, 2);
                rp1 += __shfl_xor_sync(0xffffffffu, rp1, 1);
                rp1 += __shfl_xor_sync(0xffffffffu, rp1, 2);
                if ((lane & 3) == 0) {
                    float* rp = q ? rowp1 : rowp0;
                    int r0 = wm * 64 + mt * 16 + (lane >> 2);
                    atomicAdd(&rp[r0],     rp0);
                    atomicAdd(&rp[r0 + 8], rp1);
                }
            }
        }

        // ---- Column sums: q0 only if offd (S11/S22); q1 always (S12/S21)
        #pragma unroll
        for (int q = 0; q < 2; q++) {
            bool docol = (q == 0) ? offd : (nq == 2);
            if (!docol) continue;
            float* cpp = q ? colp1 : colp0;
            #pragma unroll
            for (int nt = 0; nt < 4; nt++)
                #pragma unroll
                for (int h = 0; h < 2; h++) {
                    float v = cp[q][nt][h];
                    v += __shfl_xor_sync(0xffffffffu, v, 4);
                    v += __shfl_xor_sync(0xffffffffu, v, 8);
                    v += __shfl_xor_sync(0xffffffffu, v, 16);
                    if (lane < 4) {
                        int c0 = wn * 32 + lane * 2 + nt * 8 + h;
                        atomicAdd(&cpp[c0], v);
                    }
                }
        }
    }
}

// ---------------------------------------------------------------------------
// Final scalar: 32 blocks x 256 threads, one row per thread.
// ---------------------------------------------------------------------------
__global__ void final_kernel(float* out) {
    __shared__ float sm[256];
    int t = threadIdx.x;
    int i = blockIdx.x * 256 + t;
    const float E5 = 148.4131591f;   // exp(1/tau), tau = 0.2

    float n1 = g_R[i]             + g_R[NROWS + i]     - E5;
    float n2 = g_R[3 * NROWS + i] + g_R[2 * NROWS + i] - E5;
    float s  = 0.5f * (logf(n1) + logf(n2)) - 5.0f * g_diag[i];

    sm[t] = s;
    __syncthreads();
    #pragma unroll
    for (int o = 128; o > 0; o >>= 1) {
        if (t < o) sm[t] += sm[t + o];
        __syncthreads();
    }
    if (t == 0) atomicAdd(out, sm[0] * (1.0f / NROWS));
}

// ---------------------------------------------------------------------------
extern "C" void kernel_launch(void* const* d_in, const int* in_sizes, int n_in,
                              void* d_out, int out_size) {
    const float* h1 = (const float*)d_in[0];
    const float* h2 = (const float*)d_in[1];
    float* out = (float*)d_out;

    cudaFuncSetAttribute(mma_exp_kernel,
                         cudaFuncAttributeMaxDynamicSharedMemorySize, SM_TOTAL);

    norm_kernel<<<(NROWS * 32) / 256, 256>>>(h1, h2, out);
    mma_exp_kernel<<<NPAIR, 256, SM_TOTAL>>>();
    final_kernel<<<NROWS / 256, 256>>>(out);
}

// round 9
// speedup vs baseline: 2.1084x; 2.1084x over previous
#include <cuda_runtime.h>
#include <cuda_fp16.h>
#include <math.h>
#include <stdint.h>

#define NROWS 8192
#define DDIM  128
#define NT    64          // 8192/128 tiles per side
#define NPAIR 2080        // 64*65/2

// Scratch (__device__ globals: allocation-free rule)
__device__ uint8_t g_h1q[NROWS * DDIM];   // e4m3 of c*normalized h1, c=sqrt(5*log2 e)
__device__ uint8_t g_h2q[NROWS * DDIM];
__device__ float g_R[4 * NROWS];          // [R11 | R12row | R12col | R22]
__device__ float g_diag[NROWS];

// ---------------------------------------------------------------------------
__device__ __forceinline__ uint32_t smem_u32(const void* p) {
    uint32_t a;
    asm("{ .reg .u64 t; cvta.to.shared.u64 t, %1; cvt.u32.u64 %0, t; }"
        : "=r"(a) : "l"(p));
    return a;
}

__device__ __forceinline__ void ldsm_x4(uint32_t& r0, uint32_t& r1,
                                        uint32_t& r2, uint32_t& r3, uint32_t addr) {
    asm volatile("ldmatrix.sync.aligned.m8n8.x4.shared.b16 {%0,%1,%2,%3}, [%4];"
                 : "=r"(r0), "=r"(r1), "=r"(r2), "=r"(r3) : "r"(addr));
}

// fp8 e4m3 MMA with f16 accumulators (2 b32 regs = 4 halves)
__device__ __forceinline__ void mma_fp8_h(uint32_t* d, const uint32_t* a, const uint32_t* b) {
    asm volatile(
        "mma.sync.aligned.m16n8k32.row.col.f16.e4m3.e4m3.f16 "
        "{%0,%1}, {%2,%3,%4,%5}, {%6,%7}, {%0,%1};"
        : "+r"(d[0]), "+r"(d[1])
        : "r"(a[0]), "r"(a[1]), "r"(a[2]), "r"(a[3]), "r"(b[0]), "r"(b[1]));
}

__device__ __forceinline__ uint32_t pack_e4m3x4(float e0, float e1, float e2, float e3) {
    uint32_t r;
    asm("{ .reg .b16 lo, hi;\n\t"
        "cvt.rn.satfinite.e4m3x2.f32 lo, %2, %1;\n\t"
        "cvt.rn.satfinite.e4m3x2.f32 hi, %4, %3;\n\t"
        "mov.b32 %0, {lo, hi}; }"
        : "=r"(r) : "f"(e0), "f"(e1), "f"(e2), "f"(e3));
    return r;
}

// ---------------------------------------------------------------------------
// Row-normalize -> e4m3 scaled by C = sqrt(5*log2(e)); exact fp32 diag;
// zero g_R and out.  acc = 5*log2(e)*s, so exp(5s) = 2^acc.
// ---------------------------------------------------------------------------
__global__ void norm_kernel(const float* __restrict__ h1,
                            const float* __restrict__ h2,
                            float* __restrict__ out) {
    int gt   = blockIdx.x * blockDim.x + threadIdx.x;
    int w    = gt >> 5;
    int lane = gt & 31;

    if (gt < 4 * NROWS) g_R[gt] = 0.0f;
    if (gt == 0) out[0] = 0.0f;
    if (w >= NROWS) return;

    float4 v1 = ((const float4*)(h1 + (size_t)w * DDIM))[lane];
    float4 v2 = ((const float4*)(h2 + (size_t)w * DDIM))[lane];

    float ss1 = v1.x*v1.x + v1.y*v1.y + v1.z*v1.z + v1.w*v1.w;
    float ss2 = v2.x*v2.x + v2.y*v2.y + v2.z*v2.z + v2.w*v2.w;
    float dt  = v1.x*v2.x + v1.y*v2.y + v1.z*v2.z + v1.w*v2.w;

    #pragma unroll
    for (int m = 16; m > 0; m >>= 1) {
        ss1 += __shfl_xor_sync(0xffffffffu, ss1, m);
        ss2 += __shfl_xor_sync(0xffffffffu, ss2, m);
        dt  += __shfl_xor_sync(0xffffffffu, dt,  m);
    }

    const float C = 2.6857914f;   // sqrt(5*log2(e))
    float in1 = 1.0f / fmaxf(sqrtf(ss1), 1e-12f);
    float in2 = 1.0f / fmaxf(sqrtf(ss2), 1e-12f);
    float s1 = C * in1, s2 = C * in2;

    ((uint32_t*)(g_h1q + (size_t)w * DDIM))[lane] =
        pack_e4m3x4(v1.x*s1, v1.y*s1, v1.z*s1, v1.w*s1);
    ((uint32_t*)(g_h2q + (size_t)w * DDIM))[lane] =
        pack_e4m3x4(v2.x*s2, v2.y*s2, v2.z*s2, v2.w*s2);

    if (lane == 0) g_diag[w] = dt * in1 * in2;
}

// ---------------------------------------------------------------------------
// Pair-CTA kernel, fp8 MMA with f16 accumulate. One CTA per pair (I<=J).
//   g0: h1[I]*h1[J]^T  row->R11[I],  col->R11[J] (J>I)
//   g1: h2[I]*h2[J]^T  row->R22[I],  col->R22[J] (J>I)
//   g2: h1[I]*h2[J]^T  row->R12r[I], col->R12c[J]
//   g3: h2[I]*h1[J]^T  row->R12c[I], col->R12r[J] (J>I only)
// acc (f16) = 5*log2(e)*s, so e = h2exp2(acc) directly.
// ---------------------------------------------------------------------------
#define SM_TILE 16384
#define SM_TOTAL (4 * SM_TILE)

__global__ void __launch_bounds__(256, 2) mma_exp_kernel() {
    extern __shared__ char smem[];
    const uint32_t sb = smem_u32(smem);

    int tid  = threadIdx.x;
    int wid  = tid >> 5;
    int lane = tid & 31;

    // Decode triangular pair index -> (I, J), I<=J
    int p = blockIdx.x, I = 0;
    while (p >= NT - I) { p -= NT - I; I++; }
    int J = I + p;
    bool offd = (J > I);

    // ---- Load 4 tiles (h1[I], h2[I], h1[J], h2[J]) into swizzled SMEM
    {
        const uint4* base[4] = {
            (const uint4*)(g_h1q + (size_t)I * 128 * DDIM),
            (const uint4*)(g_h2q + (size_t)I * 128 * DDIM),
            (const uint4*)(g_h1q + (size_t)J * 128 * DDIM),
            (const uint4*)(g_h2q + (size_t)J * 128 * DDIM)
        };
        #pragma unroll
        for (int it = 0; it < 16; it++) {
            int tile = it >> 2;
            int lidx = tid + (it & 3) * 256;
            int r = lidx >> 3, c = lidx & 7;
            uint32_t off = (uint32_t)tile * SM_TILE + (uint32_t)r * 128u
                         + (uint32_t)((c ^ (r & 7)) << 4);
            *(uint4*)(smem + off) = base[tile][lidx];
        }
    }
    __syncthreads();

    int wm = wid >> 2;          // 0..1  (M)
    int wn = wid & 3;           // 0..3  (N)
    int a_r  = wm * 64 + (lane & 15);
    int a_cp = lane >> 4;
    int b_r  = wn * 32 + ((lane >> 4) << 3) + (lane & 7);
    int b_cp = (lane >> 3) & 1;

    int ngemm = offd ? 4 : 3;

    #pragma unroll 1
    for (int g = 0; g < ngemm; g++) {
        // A from I-side tiles {0:h1I,1:h2I}, B from J-side {2:h1J,3:h2J}
        uint32_t As = ((g == 1 || g == 3) ? 1u : 0u) * SM_TILE;
        uint32_t Bs = ((g == 1 || g == 2) ? 3u : 2u) * SM_TILE;

        float* Rrow; float* Rcol; bool docol;
        if (g == 0)      { Rrow = g_R + I*128;             Rcol = g_R + J*128;             docol = offd; }
        else if (g == 1) { Rrow = g_R + 3*NROWS + I*128;   Rcol = g_R + 3*NROWS + J*128;   docol = offd; }
        else if (g == 2) { Rrow = g_R + NROWS + I*128;     Rcol = g_R + 2*NROWS + J*128;   docol = true; }
        else             { Rrow = g_R + 2*NROWS + I*128;   Rcol = g_R + NROWS + J*128;     docol = true; }

        // ---- Preload ALL B fragments for this GEMM (8 LDSM, 32 regs)
        uint32_t b[4][4][2];   // [kstep][ntile][half]
        #pragma unroll
        for (int ks = 0; ks < 4; ks++) {
            int kc = ks * 2;
            #pragma unroll
            for (int np = 0; np < 2; np++) {
                int r = b_r + np * 16;
                uint32_t addr = sb + Bs + (uint32_t)r * 128u
                              + (uint32_t)(((kc + b_cp) ^ (r & 7)) << 4);
                ldsm_x4(b[ks][np*2][0], b[ks][np*2][1],
                        b[ks][np*2+1][0], b[ks][np*2+1][1], addr);
            }
        }

        __half2 cp[4];   // per-ntile packed col-pair sums
        #pragma unroll
        for (int nt = 0; nt < 4; nt++) cp[nt] = __half2half2(__ushort_as_half(0));

        // ---- 4 independent strips of 16 rows: MMA + fused epilogue
        #pragma unroll
        for (int mt = 0; mt < 4; mt++) {
            uint32_t a[4][4];
            int r = a_r + mt * 16;
            #pragma unroll
            for (int ks = 0; ks < 4; ks++) {
                uint32_t addr = sb + As + (uint32_t)r * 128u
                              + (uint32_t)(((ks * 2 + a_cp) ^ (r & 7)) << 4);
                ldsm_x4(a[ks][0], a[ks][1], a[ks][2], a[ks][3], addr);
            }

            uint32_t acc[4][2];   // f16x2 accumulators per ntile
            #pragma unroll
            for (int nt = 0; nt < 4; nt++) { acc[nt][0] = 0u; acc[nt][1] = 0u; }

            #pragma unroll
            for (int ks = 0; ks < 4; ks++)
                #pragma unroll
                for (int nt = 0; nt < 4; nt++)
                    mma_fp8_h(acc[nt], a[ks], b[ks][nt]);

            // Strip epilogue: e = 2^acc, packed half2 throughout
            __half2 rpA = __half2half2(__ushort_as_half(0));  // (row r: c0,c1)
            __half2 rpB = rpA;                                 // (row r+8: c2,c3)
            #pragma unroll
            for (int nt = 0; nt < 4; nt++) {
                __half2 e01 = h2exp2(*(__half2*)&acc[nt][0]);
                __half2 e23 = h2exp2(*(__half2*)&acc[nt][1]);
                rpA = __hadd2(rpA, e01);
                rpB = __hadd2(rpB, e23);
                cp[nt] = __hadd2(cp[nt], __hadd2(e01, e23));   // (e0+e2, e1+e3)
            }
            rpA = __hadd2(rpA, __shfl_xor_sync(0xffffffffu, rpA, 1));
            rpA = __hadd2(rpA, __shfl_xor_sync(0xffffffffu, rpA, 2));
            rpB = __hadd2(rpB, __shfl_xor_sync(0xffffffffu, rpB, 1));
            rpB = __hadd2(rpB, __shfl_xor_sync(0xffffffffu, rpB, 2));
            if ((lane & 3) == 0) {
                int r0 = wm * 64 + mt * 16 + (lane >> 2);
                atomicAdd(&Rrow[r0],     __low2float(rpA) + __high2float(rpA));
                atomicAdd(&Rrow[r0 + 8], __low2float(rpB) + __high2float(rpB));
            }
        }

        // ---- Column sums for this GEMM
        if (docol) {
            #pragma unroll
            for (int nt = 0; nt < 4; nt++) {
                __half2 v = cp[nt];
                v = __hadd2(v, __shfl_xor_sync(0xffffffffu, v, 4));
                v = __hadd2(v, __shfl_xor_sync(0xffffffffu, v, 8));
                v = __hadd2(v, __shfl_xor_sync(0xffffffffu, v, 16));
                if (lane < 4) {
                    int c0 = wn * 32 + lane * 2 + nt * 8;
                    atomicAdd(&Rcol[c0],     __low2float(v));
                    atomicAdd(&Rcol[c0 + 1], __high2float(v));
                }
            }
        }
    }
}

// ---------------------------------------------------------------------------
// Final scalar: 32 blocks x 256 threads, one row per thread.
// ---------------------------------------------------------------------------
__global__ void final_kernel(float* out) {
    __shared__ float sm[256];
    int t = threadIdx.x;
    int i = blockIdx.x * 256 + t;
    const float E5 = 148.4131591f;   // exp(1/tau), tau = 0.2

    float n1 = g_R[i]             + g_R[NROWS + i]     - E5;
    float n2 = g_R[3 * NROWS + i] + g_R[2 * NROWS + i] - E5;
    float s  = 0.5f * (logf(n1) + logf(n2)) - 5.0f * g_diag[i];

    sm[t] = s;
    __syncthreads();
    #pragma unroll
    for (int o = 128; o > 0; o >>= 1) {
        if (t < o) sm[t] += sm[t + o];
        __syncthreads();
    }
    if (t == 0) atomicAdd(out, sm[0] * (1.0f / NROWS));
}

// ---------------------------------------------------------------------------
extern "C" void kernel_launch(void* const* d_in, const int* in_sizes, int n_in,
                              void* d_out, int out_size) {
    const float* h1 = (const float*)d_in[0];
    const float* h2 = (const float*)d_in[1];
    float* out = (float*)d_out;

    cudaFuncSetAttribute(mma_exp_kernel,
                         cudaFuncAttributeMaxDynamicSharedMemorySize, SM_TOTAL);

    norm_kernel<<<(NROWS * 32) / 256, 256>>>(h1, h2, out);
    mma_exp_kernel<<<NPAIR, 256, SM_TOTAL>>>();
    final_kernel<<<NROWS / 256, 256>>>(out);
}